// round 2
// baseline (speedup 1.0000x reference)
#include <cuda_runtime.h>
#include <cuda_bf16.h>

// ---------------------------------------------------------------------------
// ResidualVQLayer: x_proj = x@W_in + b_in ; 4-stage RVQ ; z_q = qsum@W_out + b_out
// Shapes: tokens N=65536 (B32 x L2048), D_IN=1024, D_RVQ=64, NQ=4, CODES=32
// Output layout (float32): [ z_q (N*1024) | indices (4*N) | vq_loss (1) ]
// ---------------------------------------------------------------------------

#define NTOK   65536
#define DIN    1024
#define DRVQ   64
#define NQ     4
#define NCODES 32
#define ZQ_ELEMS   ((long long)NTOK * DIN)       // 67108864
#define IDX_ELEMS  ((long long)NQ * NTOK)        // 262144

// Scratch (device globals: allocation-guard safe)
__device__ float g_xproj[(size_t)NTOK * DRVQ];
__device__ float g_qsum [(size_t)NTOK * DRVQ];
__device__ float g_loss [NTOK];
__device__ float g_idx_sink[IDX_ELEMS + 1];      // fallback if out layout differs

// ---------------- packed f32x2 helpers (FFMA-wide) -------------------------
__device__ __forceinline__ void fma2(unsigned long long& d,
                                     unsigned long long a,
                                     unsigned long long b) {
    asm("fma.rn.f32x2 %0, %1, %2, %0;" : "+l"(d) : "l"(a), "l"(b));
}
__device__ __forceinline__ unsigned long long dup2(float v) {
    unsigned long long r;
    asm("mov.b64 %0, {%1, %1};" : "=l"(r) : "f"(v));
    return r;
}
__device__ __forceinline__ float2 unpack2(unsigned long long v) {
    float2 r;
    asm("mov.b64 {%0, %1}, %2;" : "=f"(r.x), "=f"(r.y) : "l"(v));
    return r;
}

// ---------------------------------------------------------------------------
// GEMM1: g_xproj[N x 64] = x[N x 1024] @ W_in[1024 x 64] + b_in
// BM=128, BN=64(full), KC=32. 256 thr; thread tile 8 rows x 4 cols via f32x2
// (rows packed in pairs -> acc[4 rowpairs][4 cols]).
// ---------------------------------------------------------------------------
__global__ __launch_bounds__(256) void gemm1_kernel(
    const float* __restrict__ x, const float* __restrict__ W,
    const float* __restrict__ bias)
{
    __shared__ float As[32][132];   // [k][m], padded
    __shared__ float Bs[32][64];    // [k][n]

    const int tid = threadIdx.x;
    const int tx  = tid & 15;       // cols tx*4 .. +3
    const int ty  = tid >> 4;       // rows ty*8 .. +7
    const int row0 = blockIdx.x * 128;

    unsigned long long acc[4][4];
#pragma unroll
    for (int i = 0; i < 4; i++)
#pragma unroll
        for (int j = 0; j < 4; j++) acc[i][j] = 0ULL;

    for (int k0 = 0; k0 < DIN; k0 += 32) {
#pragma unroll
        for (int it = 0; it < 4; it++) {            // A: 128x32 = 1024 float4
            int i = tid + it * 256;
            int m  = i >> 3;
            int kv = (i & 7) << 2;
            float4 v = *(const float4*)(x + (size_t)(row0 + m) * DIN + k0 + kv);
            As[kv + 0][m] = v.x;
            As[kv + 1][m] = v.y;
            As[kv + 2][m] = v.z;
            As[kv + 3][m] = v.w;
        }
#pragma unroll
        for (int it = 0; it < 2; it++) {            // B: 32x64 = 512 float4
            int i = tid + it * 256;
            int kk = i >> 4;
            int nv = (i & 15) << 2;
            *(float4*)&Bs[kk][nv] =
                *(const float4*)(W + (size_t)(k0 + kk) * DRVQ + nv);
        }
        __syncthreads();

#pragma unroll
        for (int kk = 0; kk < 32; kk++) {
            unsigned long long a2[4];
#pragma unroll
            for (int i = 0; i < 4; i++)
                a2[i] = *(const unsigned long long*)&As[kk][ty * 8 + i * 2];
            float4 bv = *(const float4*)&Bs[kk][tx * 4];
            unsigned long long b0 = dup2(bv.x), b1 = dup2(bv.y);
            unsigned long long b2 = dup2(bv.z), b3 = dup2(bv.w);
#pragma unroll
            for (int i = 0; i < 4; i++) {
                fma2(acc[i][0], a2[i], b0);
                fma2(acc[i][1], a2[i], b1);
                fma2(acc[i][2], a2[i], b2);
                fma2(acc[i][3], a2[i], b3);
            }
        }
        __syncthreads();
    }

    float bb[4];
#pragma unroll
    for (int j = 0; j < 4; j++) bb[j] = bias[tx * 4 + j];
#pragma unroll
    for (int i = 0; i < 4; i++) {
        float2 c0 = unpack2(acc[i][0]);
        float2 c1 = unpack2(acc[i][1]);
        float2 c2 = unpack2(acc[i][2]);
        float2 c3 = unpack2(acc[i][3]);
        int r = row0 + ty * 8 + i * 2;
        float4 o0 = {c0.x + bb[0], c1.x + bb[1], c2.x + bb[2], c3.x + bb[3]};
        float4 o1 = {c0.y + bb[0], c1.y + bb[1], c2.y + bb[2], c3.y + bb[3]};
        *(float4*)(g_xproj + (size_t)r * DRVQ + tx * 4)       = o0;
        *(float4*)(g_xproj + (size_t)(r + 1) * DRVQ + tx * 4) = o1;
    }
}

// ---------------------------------------------------------------------------
// RVQ: per token (64-dim), 4 sequential quantizers. One warp per token, lane =
// code index. dist = c2 - 2*dot (argmin-equivalent); loss adds exact r2 back.
// 4 tokens per warp to amortize the 32KB codebook smem staging.
// ---------------------------------------------------------------------------
__global__ __launch_bounds__(256) void rvq_kernel(
    const float* __restrict__ cb, float* __restrict__ out_idx)
{
    __shared__ float4 cbT4[NQ][16][NCODES];       // [q][d/4][c]  (32 KB)
    __shared__ float  c2s[NQ][NCODES];
    __shared__ __align__(16) float rs[8][DRVQ];

    const int tid = threadIdx.x;
    for (int i = tid; i < NQ * 16 * NCODES; i += 256) {
        int q  = i >> 9;
        int dd = (i >> 5) & 15;
        int c  = i & 31;
        const float* p = cb + ((size_t)(q * NCODES + c) * DRVQ + dd * 4);
        cbT4[q][dd][c] = make_float4(p[0], p[1], p[2], p[3]);
    }
    __syncthreads();
    if (tid < NQ * NCODES) {
        int q = tid >> 5, c = tid & 31;
        float s = 0.f;
#pragma unroll
        for (int dd = 0; dd < 16; dd++) {
            float4 v = cbT4[q][dd][c];
            s += v.x * v.x + v.y * v.y + v.z * v.z + v.w * v.w;
        }
        c2s[q][c] = s;
    }
    __syncthreads();

    const int wid = tid >> 5, lane = tid & 31;
    float* rsw = rs[wid];

#pragma unroll 1
    for (int it = 0; it < 4; it++) {
        int t = (blockIdx.x * 8 + wid) * 4 + it;
        rsw[lane]      = g_xproj[(size_t)t * DRVQ + lane];
        rsw[lane + 32] = g_xproj[(size_t)t * DRVQ + 32 + lane];
        float q0 = 0.f, q1 = 0.f, lacc = 0.f;
        __syncwarp();

#pragma unroll
        for (int q = 0; q < NQ; q++) {
            // exact residual norm^2 (needed for the loss term)
            float r2p = rsw[lane] * rsw[lane] + rsw[lane + 32] * rsw[lane + 32];
#pragma unroll
            for (int off = 16; off; off >>= 1)
                r2p += __shfl_xor_sync(0xffffffffu, r2p, off);

            // lane c: dot(residual, code c) via float4 broadcast reads
            float dot = 0.f;
            const float4* rp = (const float4*)rsw;
#pragma unroll
            for (int dd = 0; dd < 16; dd++) {
                float4 rv = rp[dd];
                float4 cv = cbT4[q][dd][lane];
                dot = fmaf(rv.x, cv.x, dot);
                dot = fmaf(rv.y, cv.y, dot);
                dot = fmaf(rv.z, cv.z, dot);
                dot = fmaf(rv.w, cv.w, dot);
            }
            float dist = c2s[q][lane] - 2.f * dot;
            int bidx = lane;
#pragma unroll
            for (int off = 16; off; off >>= 1) {   // lexicographic (dist, idx) min
                float od = __shfl_xor_sync(0xffffffffu, dist, off);
                int   oi = __shfl_xor_sync(0xffffffffu, bidx, off);
                if (od < dist || (od == dist && oi < bidx)) { dist = od; bidx = oi; }
            }
            lacc += r2p + dist;                    // = ||residual - code||^2
            if (lane == 0) out_idx[(size_t)q * NTOK + t] = (float)bidx;

            const float* cvec = cb + (size_t)(q * NCODES + bidx) * DRVQ;
            float c0 = cvec[lane], c1 = cvec[lane + 32];
            q0 += c0; q1 += c1;
            __syncwarp();
            rsw[lane]      -= c0;
            rsw[lane + 32] -= c1;
            __syncwarp();
        }
        g_qsum[(size_t)t * DRVQ + lane]      = q0;
        g_qsum[(size_t)t * DRVQ + 32 + lane] = q1;
        if (lane == 0) g_loss[t] = lacc;
        __syncwarp();
    }
}

// ---------------------------------------------------------------------------
// Deterministic loss reduction: vq_loss = sum(g_loss) / (NTOK * DRVQ)
// ---------------------------------------------------------------------------
__global__ __launch_bounds__(256) void loss_kernel(float* __restrict__ out)
{
    __shared__ float sm[256];
    float s = 0.f;
    for (int i = threadIdx.x; i < NTOK; i += 256) s += g_loss[i];
    sm[threadIdx.x] = s;
    __syncthreads();
#pragma unroll
    for (int o = 128; o > 0; o >>= 1) {
        if (threadIdx.x < o) sm[threadIdx.x] += sm[threadIdx.x + o];
        __syncthreads();
    }
    if (threadIdx.x == 0) out[0] = sm[0] * (1.f / ((float)NTOK * (float)DRVQ));
}

// ---------------------------------------------------------------------------
// GEMM2: out[N x 1024] = g_qsum[N x 64] @ W_out[64 x 1024] + b_out
// BM=64, BN=128, K=64 fully resident. Thread tile 4 rows x 8 cols; cols packed
// in pairs (natural 64-bit loads from Bs, conflict-free: col = 2*tx + 32*jj).
// ---------------------------------------------------------------------------
__global__ __launch_bounds__(256) void gemm2_kernel(
    const float* __restrict__ W, const float* __restrict__ bias,
    float* __restrict__ out)
{
    __shared__ float As[64][64];    // [m][k]
    __shared__ float Bs[64][128];   // [k][n]

    const int tid = threadIdx.x;
    const int tx  = tid & 15;
    const int ty  = tid >> 4;
    const int row0 = blockIdx.x * 64;
    const int n0   = blockIdx.y * 128;

#pragma unroll
    for (int it = 0; it < 4; it++) {               // A: 64x64
        int i  = tid + it * 256;
        int m  = i >> 4;
        int kv = (i & 15) << 2;
        *(float4*)&As[m][kv] =
            *(const float4*)(g_qsum + (size_t)(row0 + m) * DRVQ + kv);
    }
#pragma unroll
    for (int it = 0; it < 8; it++) {               // B: 64x128
        int i  = tid + it * 256;
        int kk = i >> 5;
        int nv = (i & 31) << 2;
        *(float4*)&Bs[kk][nv] =
            *(const float4*)(W + (size_t)kk * DIN + n0 + nv);
    }
    __syncthreads();

    unsigned long long acc[4][4];                  // [row][colpair]
#pragma unroll
    for (int i = 0; i < 4; i++)
#pragma unroll
        for (int j = 0; j < 4; j++) acc[i][j] = 0ULL;

#pragma unroll
    for (int kk = 0; kk < 64; kk++) {
        unsigned long long b2[4];
#pragma unroll
        for (int jj = 0; jj < 4; jj++)
            b2[jj] = *(const unsigned long long*)&Bs[kk][tx * 2 + jj * 32];
#pragma unroll
        for (int i = 0; i < 4; i++) {
            unsigned long long ad = dup2(As[ty * 4 + i][kk]);
            fma2(acc[i][0], ad, b2[0]);
            fma2(acc[i][1], ad, b2[1]);
            fma2(acc[i][2], ad, b2[2]);
            fma2(acc[i][3], ad, b2[3]);
        }
    }

#pragma unroll
    for (int i = 0; i < 4; i++) {
        int row = row0 + ty * 4 + i;
#pragma unroll
        for (int jj = 0; jj < 4; jj++) {
            int col = n0 + tx * 2 + jj * 32;
            float2 c = unpack2(acc[i][jj]);
            c.x += bias[col];
            c.y += bias[col + 1];
            *(float2*)(out + (size_t)row * DIN + col) = c;
        }
    }
}

// ---------------------------------------------------------------------------
extern "C" void kernel_launch(void* const* d_in, const int* in_sizes, int n_in,
                              void* d_out, int out_size)
{
    const float* x     = (const float*)d_in[0];
    const float* W_in  = (const float*)d_in[1];
    const float* b_in  = (const float*)d_in[2];
    const float* cb    = (const float*)d_in[3];
    const float* W_out = (const float*)d_in[4];
    const float* b_out = (const float*)d_in[5];
    float* out = (float*)d_out;

    // Expected layout: [ z_q | indices | loss ]. If out is smaller than that,
    // park the aux outputs in device scratch so the kernels stay identical.
    const long long full = ZQ_ELEMS + IDX_ELEMS + 1;
    float* idx_dst;
    float* loss_dst;
    if ((long long)out_size >= full) {
        idx_dst  = out + ZQ_ELEMS;
        loss_dst = out + ZQ_ELEMS + IDX_ELEMS;
    } else {
        float* sink = nullptr;
        cudaGetSymbolAddress((void**)&sink, g_idx_sink);  // query only; capture-safe
        idx_dst  = sink;
        loss_dst = sink + IDX_ELEMS;
    }

    gemm1_kernel<<<NTOK / 128, 256>>>(x, W_in, b_in);
    rvq_kernel<<<NTOK / 32, 256>>>(cb, idx_dst);
    loss_kernel<<<1, 256>>>(loss_dst);
    gemm2_kernel<<<dim3(NTOK / 64, DIN / 128), 256>>>(W_out, b_out, out);
}

// round 3
// speedup vs baseline: 1.0037x; 1.0037x over previous
#include <cuda_runtime.h>
#include <cuda_bf16.h>

// ---------------------------------------------------------------------------
// ResidualVQLayer: x_proj = x@W_in + b_in ; 4-stage RVQ ; z_q = qsum@W_out + b_out
// Shapes: tokens N=65536 (B32 x L2048), D_IN=1024, D_RVQ=64, NQ=4, CODES=32
// Output layout (float32): [ z_q (N*1024) | indices (4*N) | vq_loss (1) ]
// ---------------------------------------------------------------------------

#define NTOK   65536
#define DIN    1024
#define DRVQ   64
#define NQ     4
#define NCODES 32
#define ZQ_ELEMS   ((long long)NTOK * DIN)       // 67108864
#define IDX_ELEMS  ((long long)NQ * NTOK)        // 262144

// Scratch (device globals: allocation-guard safe)
__device__ float g_xproj[(size_t)NTOK * DRVQ];
__device__ float g_qsum [(size_t)NTOK * DRVQ];
__device__ float g_loss [NTOK];
__device__ float g_idx_sink[IDX_ELEMS + 1];      // fallback if out layout differs

// ---------------- packed f32x2 helpers (FFMA-wide) -------------------------
__device__ __forceinline__ void fma2(unsigned long long& d,
                                     unsigned long long a,
                                     unsigned long long b) {
    asm("fma.rn.f32x2 %0, %1, %2, %0;" : "+l"(d) : "l"(a), "l"(b));
}
__device__ __forceinline__ unsigned long long dup2(float v) {
    unsigned long long r;
    asm("mov.b64 %0, {%1, %1};" : "=l"(r) : "f"(v));
    return r;
}
__device__ __forceinline__ float2 unpack2(unsigned long long v) {
    float2 r;
    asm("mov.b64 {%0, %1}, %2;" : "=f"(r.x), "=f"(r.y) : "l"(v));
    return r;
}

// ---------------------------------------------------------------------------
// GEMM1: g_xproj[N x 64] = x[N x 1024] @ W_in[1024 x 64] + b_in
// BM=128, BN=64(full), KC=32. 256 thr; thread tile 8 rows x 4 cols via f32x2
// (rows packed in pairs -> acc[4 rowpairs][4 cols]).
// ---------------------------------------------------------------------------
__global__ __launch_bounds__(256) void gemm1_kernel(
    const float* __restrict__ x, const float* __restrict__ W,
    const float* __restrict__ bias)
{
    __shared__ float As[32][132];   // [k][m], padded
    __shared__ float Bs[32][64];    // [k][n]

    const int tid = threadIdx.x;
    const int tx  = tid & 15;       // cols tx*4 .. +3
    const int ty  = tid >> 4;       // rows ty*8 .. +7
    const int row0 = blockIdx.x * 128;

    unsigned long long acc[4][4];
#pragma unroll
    for (int i = 0; i < 4; i++)
#pragma unroll
        for (int j = 0; j < 4; j++) acc[i][j] = 0ULL;

    for (int k0 = 0; k0 < DIN; k0 += 32) {
#pragma unroll
        for (int it = 0; it < 4; it++) {            // A: 128x32 = 1024 float4
            int i = tid + it * 256;
            int m  = i >> 3;
            int kv = (i & 7) << 2;
            float4 v = *(const float4*)(x + (size_t)(row0 + m) * DIN + k0 + kv);
            As[kv + 0][m] = v.x;
            As[kv + 1][m] = v.y;
            As[kv + 2][m] = v.z;
            As[kv + 3][m] = v.w;
        }
#pragma unroll
        for (int it = 0; it < 2; it++) {            // B: 32x64 = 512 float4
            int i = tid + it * 256;
            int kk = i >> 4;
            int nv = (i & 15) << 2;
            *(float4*)&Bs[kk][nv] =
                *(const float4*)(W + (size_t)(k0 + kk) * DRVQ + nv);
        }
        __syncthreads();

#pragma unroll
        for (int kk = 0; kk < 32; kk++) {
            unsigned long long a2[4];
#pragma unroll
            for (int i = 0; i < 4; i++)
                a2[i] = *(const unsigned long long*)&As[kk][ty * 8 + i * 2];
            float4 bv = *(const float4*)&Bs[kk][tx * 4];
            unsigned long long b0 = dup2(bv.x), b1 = dup2(bv.y);
            unsigned long long b2 = dup2(bv.z), b3 = dup2(bv.w);
#pragma unroll
            for (int i = 0; i < 4; i++) {
                fma2(acc[i][0], a2[i], b0);
                fma2(acc[i][1], a2[i], b1);
                fma2(acc[i][2], a2[i], b2);
                fma2(acc[i][3], a2[i], b3);
            }
        }
        __syncthreads();
    }

    float bb[4];
#pragma unroll
    for (int j = 0; j < 4; j++) bb[j] = bias[tx * 4 + j];
#pragma unroll
    for (int i = 0; i < 4; i++) {
        float2 c0 = unpack2(acc[i][0]);
        float2 c1 = unpack2(acc[i][1]);
        float2 c2 = unpack2(acc[i][2]);
        float2 c3 = unpack2(acc[i][3]);
        int r = row0 + ty * 8 + i * 2;
        float4 o0 = {c0.x + bb[0], c1.x + bb[1], c2.x + bb[2], c3.x + bb[3]};
        float4 o1 = {c0.y + bb[0], c1.y + bb[1], c2.y + bb[2], c3.y + bb[3]};
        *(float4*)(g_xproj + (size_t)r * DRVQ + tx * 4)       = o0;
        *(float4*)(g_xproj + (size_t)(r + 1) * DRVQ + tx * 4) = o1;
    }
}

// ---------------------------------------------------------------------------
// RVQ: per token (64-dim), 4 sequential quantizers. One warp per token, lane =
// code index. dist = c2 - 2*dot (argmin-equivalent); loss adds exact r2 back.
// 4 tokens per warp to amortize the 32KB codebook smem staging.
// ---------------------------------------------------------------------------
__global__ __launch_bounds__(256) void rvq_kernel(
    const float* __restrict__ cb, float* __restrict__ out_idx)
{
    __shared__ float4 cbT4[NQ][16][NCODES];       // [q][d/4][c]  (32 KB)
    __shared__ float  c2s[NQ][NCODES];
    __shared__ __align__(16) float rs[8][DRVQ];

    const int tid = threadIdx.x;
    for (int i = tid; i < NQ * 16 * NCODES; i += 256) {
        int q  = i >> 9;
        int dd = (i >> 5) & 15;
        int c  = i & 31;
        const float* p = cb + ((size_t)(q * NCODES + c) * DRVQ + dd * 4);
        cbT4[q][dd][c] = make_float4(p[0], p[1], p[2], p[3]);
    }
    __syncthreads();
    if (tid < NQ * NCODES) {
        int q = tid >> 5, c = tid & 31;
        float s = 0.f;
#pragma unroll
        for (int dd = 0; dd < 16; dd++) {
            float4 v = cbT4[q][dd][c];
            s += v.x * v.x + v.y * v.y + v.z * v.z + v.w * v.w;
        }
        c2s[q][c] = s;
    }
    __syncthreads();

    const int wid = tid >> 5, lane = tid & 31;
    float* rsw = rs[wid];

#pragma unroll 1
    for (int it = 0; it < 4; it++) {
        int t = (blockIdx.x * 8 + wid) * 4 + it;
        rsw[lane]      = g_xproj[(size_t)t * DRVQ + lane];
        rsw[lane + 32] = g_xproj[(size_t)t * DRVQ + 32 + lane];
        float q0 = 0.f, q1 = 0.f, lacc = 0.f;
        __syncwarp();

#pragma unroll
        for (int q = 0; q < NQ; q++) {
            // exact residual norm^2 (needed for the loss term)
            float r2p = rsw[lane] * rsw[lane] + rsw[lane + 32] * rsw[lane + 32];
#pragma unroll
            for (int off = 16; off; off >>= 1)
                r2p += __shfl_xor_sync(0xffffffffu, r2p, off);

            // lane c: dot(residual, code c) via float4 broadcast reads
            float dot = 0.f;
            const float4* rp = (const float4*)rsw;
#pragma unroll
            for (int dd = 0; dd < 16; dd++) {
                float4 rv = rp[dd];
                float4 cv = cbT4[q][dd][lane];
                dot = fmaf(rv.x, cv.x, dot);
                dot = fmaf(rv.y, cv.y, dot);
                dot = fmaf(rv.z, cv.z, dot);
                dot = fmaf(rv.w, cv.w, dot);
            }
            float dist = c2s[q][lane] - 2.f * dot;
            int bidx = lane;
#pragma unroll
            for (int off = 16; off; off >>= 1) {   // lexicographic (dist, idx) min
                float od = __shfl_xor_sync(0xffffffffu, dist, off);
                int   oi = __shfl_xor_sync(0xffffffffu, bidx, off);
                if (od < dist || (od == dist && oi < bidx)) { dist = od; bidx = oi; }
            }
            lacc += r2p + dist;                    // = ||residual - code||^2
            if (lane == 0) out_idx[(size_t)q * NTOK + t] = (float)bidx;

            const float* cvec = cb + (size_t)(q * NCODES + bidx) * DRVQ;
            float c0 = cvec[lane], c1 = cvec[lane + 32];
            q0 += c0; q1 += c1;
            __syncwarp();
            rsw[lane]      -= c0;
            rsw[lane + 32] -= c1;
            __syncwarp();
        }
        g_qsum[(size_t)t * DRVQ + lane]      = q0;
        g_qsum[(size_t)t * DRVQ + 32 + lane] = q1;
        if (lane == 0) g_loss[t] = lacc;
        __syncwarp();
    }
}

// ---------------------------------------------------------------------------
// Deterministic loss reduction: vq_loss = sum(g_loss) / (NTOK * DRVQ)
// ---------------------------------------------------------------------------
__global__ __launch_bounds__(256) void loss_kernel(float* __restrict__ out)
{
    __shared__ float sm[256];
    float s = 0.f;
    for (int i = threadIdx.x; i < NTOK; i += 256) s += g_loss[i];
    sm[threadIdx.x] = s;
    __syncthreads();
#pragma unroll
    for (int o = 128; o > 0; o >>= 1) {
        if (threadIdx.x < o) sm[threadIdx.x] += sm[threadIdx.x + o];
        __syncthreads();
    }
    if (threadIdx.x == 0) out[0] = sm[0] * (1.f / ((float)NTOK * (float)DRVQ));
}

// ---------------------------------------------------------------------------
// GEMM2: out[N x 1024] = g_qsum[N x 64] @ W_out[64 x 1024] + b_out
// BM=64, BN=128, K=64 fully resident. Thread tile 4 rows x 8 cols; cols packed
// in pairs (natural 64-bit loads from Bs, conflict-free: col = 2*tx + 32*jj).
// ---------------------------------------------------------------------------
__global__ __launch_bounds__(256) void gemm2_kernel(
    const float* __restrict__ W, const float* __restrict__ bias,
    float* __restrict__ out)
{
    __shared__ float As[64][64];    // [m][k]
    __shared__ float Bs[64][128];   // [k][n]

    const int tid = threadIdx.x;
    const int tx  = tid & 15;
    const int ty  = tid >> 4;
    const int row0 = blockIdx.x * 64;
    const int n0   = blockIdx.y * 128;

#pragma unroll
    for (int it = 0; it < 4; it++) {               // A: 64x64
        int i  = tid + it * 256;
        int m  = i >> 4;
        int kv = (i & 15) << 2;
        *(float4*)&As[m][kv] =
            *(const float4*)(g_qsum + (size_t)(row0 + m) * DRVQ + kv);
    }
#pragma unroll
    for (int it = 0; it < 8; it++) {               // B: 64x128
        int i  = tid + it * 256;
        int kk = i >> 5;
        int nv = (i & 31) << 2;
        *(float4*)&Bs[kk][nv] =
            *(const float4*)(W + (size_t)kk * DIN + n0 + nv);
    }
    __syncthreads();

    unsigned long long acc[4][4];                  // [row][colpair]
#pragma unroll
    for (int i = 0; i < 4; i++)
#pragma unroll
        for (int j = 0; j < 4; j++) acc[i][j] = 0ULL;

#pragma unroll
    for (int kk = 0; kk < 64; kk++) {
        unsigned long long b2[4];
#pragma unroll
        for (int jj = 0; jj < 4; jj++)
            b2[jj] = *(const unsigned long long*)&Bs[kk][tx * 2 + jj * 32];
#pragma unroll
        for (int i = 0; i < 4; i++) {
            unsigned long long ad = dup2(As[ty * 4 + i][kk]);
            fma2(acc[i][0], ad, b2[0]);
            fma2(acc[i][1], ad, b2[1]);
            fma2(acc[i][2], ad, b2[2]);
            fma2(acc[i][3], ad, b2[3]);
        }
    }

#pragma unroll
    for (int i = 0; i < 4; i++) {
        int row = row0 + ty * 4 + i;
#pragma unroll
        for (int jj = 0; jj < 4; jj++) {
            int col = n0 + tx * 2 + jj * 32;
            float2 c = unpack2(acc[i][jj]);
            c.x += bias[col];
            c.y += bias[col + 1];
            *(float2*)(out + (size_t)row * DIN + col) = c;
        }
    }
}

// ---------------------------------------------------------------------------
extern "C" void kernel_launch(void* const* d_in, const int* in_sizes, int n_in,
                              void* d_out, int out_size)
{
    const float* x     = (const float*)d_in[0];
    const float* W_in  = (const float*)d_in[1];
    const float* b_in  = (const float*)d_in[2];
    const float* cb    = (const float*)d_in[3];
    const float* W_out = (const float*)d_in[4];
    const float* b_out = (const float*)d_in[5];
    float* out = (float*)d_out;

    // Expected layout: [ z_q | indices | loss ]. If out is smaller than that,
    // park the aux outputs in device scratch so the kernels stay identical.
    const long long full = ZQ_ELEMS + IDX_ELEMS + 1;
    float* idx_dst;
    float* loss_dst;
    if ((long long)out_size >= full) {
        idx_dst  = out + ZQ_ELEMS;
        loss_dst = out + ZQ_ELEMS + IDX_ELEMS;
    } else {
        float* sink = nullptr;
        cudaGetSymbolAddress((void**)&sink, g_idx_sink);  // query only; capture-safe
        idx_dst  = sink;
        loss_dst = sink + IDX_ELEMS;
    }

    gemm1_kernel<<<NTOK / 128, 256>>>(x, W_in, b_in);
    rvq_kernel<<<NTOK / 32, 256>>>(cb, idx_dst);
    loss_kernel<<<1, 256>>>(loss_dst);
    gemm2_kernel<<<dim3(NTOK / 64, DIN / 128), 256>>>(W_out, b_out, out);
}